// round 1
// baseline (speedup 1.0000x reference)
#include <cuda_runtime.h>

// Additive (Bahdanau) attention, fused.
// B=2, L=S=512, H=8, E=32, D=64.
// scores[b,h,l,s] = sum_e tanh(q[b,l,h,e] + k[b,s,h,e]) * v[e] + attn_mask[l,s] + key_len[b,s]
// A = softmax_s(scores); out[b,l,h,d] = sum_s A * values[b,s,h,d]
//
// Key trick: tanh(a+b) = (tanh a + tanh b)/(1 + tanh a * tanh b)  (exact identity).
// Precompute tanh(q), tanh(k) once (cheap), so the O(B*H*L*S*E)=134M inner loop
// needs only 1 MUFU.RCP + 4 FMA-pipe ops per element.

#define B_  2
#define L_  512
#define S_  512
#define H_  8
#define E_  32
#define D_  64
#define TL  16          // L-rows per CTA
#define SC  128         // S-chunk streamed through SMEM
#define NCH (S_/SC)     // 4
#define NT  256         // threads per CTA

#define KS_PAD 33       // padded k-chunk row stride (bank-conflict free)

__device__ __forceinline__ float rcp_(float x) {
    float r; asm("rcp.approx.f32 %0, %1;" : "=f"(r) : "f"(x)); return r;
}
__device__ __forceinline__ float ex2_(float x) {
    float r; asm("ex2.approx.f32 %0, %1;" : "=f"(r) : "f"(x)); return r;
}
// Accurate tanh: 1 - 2/(exp(2x)+1); ex2.approx rel err ~2^-22, rcp ~1ulp.
// Saturates correctly for large |x| (ex2 -> inf -> rcp -> 0; ex2 -> 0 -> -1).
__device__ __forceinline__ float tanh_acc(float x) {
    float e = ex2_(x * 2.8853900817779268f);   // 2*log2(e)
    return 1.0f - 2.0f * rcp_(e + 1.0f);
}

__global__ void __launch_bounds__(NT)
addattn_kernel(const float* __restrict__ q,
               const float* __restrict__ k,
               const float* __restrict__ val,
               const float* __restrict__ v,
               const float* __restrict__ am,
               const float* __restrict__ kl,
               float* __restrict__ out)
{
    extern __shared__ float sm[];
    float* TQ  = sm;                    // TL*E   tanh(q) tile
    float* WS  = TQ  + TL * E_;         // E      v vector
    float* SCO = WS  + E_;              // TL*S   scores -> A
    float* KS  = SCO + TL * S_;         // SC*KS_PAD tanh(k) chunk  (union w/ VS: SC*D)
    float* VS  = KS;

    const int t  = threadIdx.x;
    const int bh = blockIdx.y;
    const int b  = bh >> 3, h = bh & 7;
    const int l0 = blockIdx.x * TL;

    // ---- preload tanh(q) tile + v ----
    if (t < E_) WS[t] = v[t];
    for (int idx = t; idx < TL * E_; idx += NT) {
        int l = idx >> 5, e = idx & 31;
        TQ[idx] = tanh_acc(q[((size_t)(b * L_ + l0 + l) * H_ + h) * E_ + e]);
    }
    __syncthreads();

    // ---- phase 1: scores ----
    const int si = t & 63;      // s-lane within chunk half
    const int lg = t >> 6;      // l-group (4 rows each)
    const float* tq0 = TQ + (lg * 4 + 0) * E_;
    const float* tq1 = TQ + (lg * 4 + 1) * E_;
    const float* tq2 = TQ + (lg * 4 + 2) * E_;
    const float* tq3 = TQ + (lg * 4 + 3) * E_;

    for (int c = 0; c < NCH; ++c) {
        // load k chunk, apply tanh, store padded
        for (int idx = t; idx < SC * E_; idx += NT) {
            int r = idx >> 5, e = idx & 31;
            KS[r * KS_PAD + e] =
                tanh_acc(k[((size_t)(b * S_ + c * SC + r) * H_ + h) * E_ + e]);
        }
        __syncthreads();

        #pragma unroll
        for (int s2 = 0; s2 < 2; ++s2) {
            const int sl = si + 64 * s2;
            const int sg = c * SC + sl;
            float a0 = 0.f, a1 = 0.f, a2 = 0.f, a3 = 0.f;
            const float* ksrow = KS + sl * KS_PAD;
            #pragma unroll
            for (int e = 0; e < E_; ++e) {
                const float tk = ksrow[e];
                const float w  = WS[e];
                float tq, num;
                tq = tq0[e]; num = tq + tk; a0 = fmaf(num * rcp_(fmaf(tq, tk, 1.f)), w, a0);
                tq = tq1[e]; num = tq + tk; a1 = fmaf(num * rcp_(fmaf(tq, tk, 1.f)), w, a1);
                tq = tq2[e]; num = tq + tk; a2 = fmaf(num * rcp_(fmaf(tq, tk, 1.f)), w, a2);
                tq = tq3[e]; num = tq + tk; a3 = fmaf(num * rcp_(fmaf(tq, tk, 1.f)), w, a3);
            }
            const float klen = kl[b * S_ + sg];
            const int lb = lg * 4;
            SCO[(lb + 0) * S_ + sg] = a0 + am[(size_t)(l0 + lb + 0) * S_ + sg] + klen;
            SCO[(lb + 1) * S_ + sg] = a1 + am[(size_t)(l0 + lb + 1) * S_ + sg] + klen;
            SCO[(lb + 2) * S_ + sg] = a2 + am[(size_t)(l0 + lb + 2) * S_ + sg] + klen;
            SCO[(lb + 3) * S_ + sg] = a3 + am[(size_t)(l0 + lb + 3) * S_ + sg] + klen;
        }
        __syncthreads();
    }

    // ---- phase 2: softmax over S per l-row (8 warps, 2 rows each) ----
    const int warp = t >> 5, lane = t & 31;
    for (int l = warp; l < TL; l += 8) {
        float* row = SCO + l * S_;
        float m = -1e30f;
        #pragma unroll
        for (int i = 0; i < S_ / 32; ++i) m = fmaxf(m, row[lane + 32 * i]);
        #pragma unroll
        for (int o = 16; o; o >>= 1) m = fmaxf(m, __shfl_xor_sync(0xffffffffu, m, o));
        float sum = 0.f;
        float eb[S_ / 32];
        #pragma unroll
        for (int i = 0; i < S_ / 32; ++i) {
            float e = ex2_((row[lane + 32 * i] - m) * 1.4426950408889634f);
            eb[i] = e; sum += e;
        }
        #pragma unroll
        for (int o = 16; o; o >>= 1) sum += __shfl_xor_sync(0xffffffffu, sum, o);
        const float inv = rcp_(sum);
        #pragma unroll
        for (int i = 0; i < S_ / 32; ++i) row[lane + 32 * i] = eb[i] * inv;
    }
    __syncthreads();

    // ---- phase 3: out = A @ V ----
    const int lo = t >> 4;      // l row (0..15)
    const int dg = t & 15;      // d group of 4
    float acc0 = 0.f, acc1 = 0.f, acc2 = 0.f, acc3 = 0.f;
    for (int c = 0; c < NCH; ++c) {
        for (int idx = t; idx < SC * D_; idx += NT) {
            int r = idx >> 6, d = idx & 63;
            VS[idx] = val[((size_t)(b * S_ + c * SC + r) * H_ + h) * D_ + d];
        }
        __syncthreads();
        const float* arow = SCO + lo * S_ + c * SC;
        #pragma unroll 8
        for (int s = 0; s < SC; ++s) {
            const float a = arow[s];
            const float4 vv = *reinterpret_cast<const float4*>(VS + s * D_ + dg * 4);
            acc0 = fmaf(a, vv.x, acc0);
            acc1 = fmaf(a, vv.y, acc1);
            acc2 = fmaf(a, vv.z, acc2);
            acc3 = fmaf(a, vv.w, acc3);
        }
        __syncthreads();
    }
    float4 o4 = make_float4(acc0, acc1, acc2, acc3);
    *reinterpret_cast<float4*>(out + ((size_t)(b * L_ + l0 + lo) * H_ + h) * D_ + dg * 4) = o4;
}

// Dynamic SMEM: TQ(512) + WS(32) + SCO(8192) + max(KS 128*33, VS 128*64)=8192 floats
static const int SMEM_BYTES = (TL * E_ + E_ + TL * S_ + SC * D_) * (int)sizeof(float);

extern "C" void kernel_launch(void* const* d_in, const int* in_sizes, int n_in,
                              void* d_out, int out_size)
{
    const float* q   = (const float*)d_in[0];
    const float* k   = (const float*)d_in[1];
    const float* val = (const float*)d_in[2];
    const float* v   = (const float*)d_in[3];
    const float* am  = (const float*)d_in[4];
    const float* kl  = (const float*)d_in[5];
    float* out = (float*)d_out;

    cudaFuncSetAttribute(addattn_kernel,
                         cudaFuncAttributeMaxDynamicSharedMemorySize, SMEM_BYTES);
    dim3 grid(L_ / TL, B_ * H_);
    addattn_kernel<<<grid, NT, SMEM_BYTES>>>(q, k, val, v, am, kl, out);
}

// round 2
// speedup vs baseline: 1.4252x; 1.4252x over previous
#include <cuda_runtime.h>

// Additive (Bahdanau) attention, fused, round 2.
// tanh(a+b) = (ta+tb)/(1+ta*tb); tanh(q), tanh(k) precomputed once into
// __device__ scratch (transposed to [b,h,*,e] for coalesced tile loads).
// Main kernel: __launch_bounds__(256,2) for 2 CTAs/SM, float4 SMEM loads,
// 8 independent rcp chains per thread.

#define B_  2
#define L_  512
#define S_  512
#define H_  8
#define E_  32
#define D_  64
#define TL  16
#define SC  128
#define NCH (S_/SC)
#define NT  256
#define KSTRIDE 36              // padded KS row stride (floats, 16B-aligned, conflict-free)

__device__ float g_tq[B_*H_*L_*E_];   // [b,h,l,e]
__device__ float g_tk[B_*H_*S_*E_];   // [b,h,s,e]

__device__ __forceinline__ float rcp_(float x) {
    float r; asm("rcp.approx.f32 %0, %1;" : "=f"(r) : "f"(x)); return r;
}
__device__ __forceinline__ float ex2_(float x) {
    float r; asm("ex2.approx.f32 %0, %1;" : "=f"(r) : "f"(x)); return r;
}
__device__ __forceinline__ float tanh_acc(float x) {
    float e = ex2_(x * 2.8853900817779268f);   // 2*log2(e)
    return 1.0f - 2.0f * rcp_(e + 1.0f);
}

// ---- pre-kernel: tanh(q) and tanh(k), transposed to [b,h,*,e] ----
__global__ void __launch_bounds__(NT) tanh_pre(const float* __restrict__ q,
                                               const float* __restrict__ k)
{
    int idx = blockIdx.x * NT + threadIdx.x;     // dest index [b,h,l,e]
    if (idx >= B_*H_*L_*E_) return;
    int e = idx & 31;
    int l = (idx >> 5) & 511;
    int h = (idx >> 14) & 7;
    int b = idx >> 17;
    int src = ((b * L_ + l) * H_ + h) * E_ + e;  // L_ == S_
    g_tq[idx] = tanh_acc(q[src]);
    g_tk[idx] = tanh_acc(k[src]);
}

__device__ __forceinline__ void upd(float tq, float tk, float w, float& a) {
    float num = tq + tk;
    float den = fmaf(tq, tk, 1.0f);
    a = fmaf(num * rcp_(den), w, a);
}

__global__ void __launch_bounds__(NT, 2)
addattn_kernel(const float* __restrict__ val,
               const float* __restrict__ v,
               const float* __restrict__ am,
               const float* __restrict__ kl,
               float* __restrict__ out)
{
    extern __shared__ float sm[];
    float* TQ  = sm;                    // TL*E
    float* WS  = TQ  + TL * E_;         // E
    float* SCO = WS  + E_;              // TL*S
    float* KS  = SCO + TL * S_;         // SC*KSTRIDE (union with VS: SC*D)
    float* VS  = KS;

    const int t  = threadIdx.x;
    const int bh = blockIdx.y;
    const int b  = bh >> 3, h = bh & 7;
    const int l0 = blockIdx.x * TL;

    // ---- phase 0: load tanh(q) tile + v ----
    if (t < E_) WS[t] = v[t];
    {
        const float* tq_src = g_tq + ((size_t)bh * L_ + l0) * E_;
        for (int i = t; i < TL * E_; i += NT) TQ[i] = tq_src[i];
    }
    __syncthreads();

    // ---- phase 1: scores ----
    const int si = t & 63;
    const int lg = t >> 6;
    const float4* wv  = (const float4*)WS;
    const float4* tqp = (const float4*)(TQ + lg * 4 * E_);

    for (int c = 0; c < NCH; ++c) {
        // coalesced float4 copy of tanh(k) chunk into padded SMEM
        {
            const float4* ksrc = (const float4*)(g_tk + ((size_t)bh * S_ + c * SC) * E_);
            for (int i = t; i < SC * (E_/4); i += NT) {
                int r = i >> 3, e4 = i & 7;
                ((float4*)(KS + r * KSTRIDE))[e4] = ksrc[i];
            }
        }
        __syncthreads();

        float a00=0.f,a01=0.f,a02=0.f,a03=0.f;
        float a10=0.f,a11=0.f,a12=0.f,a13=0.f;
        const float4* k0p = (const float4*)(KS + si * KSTRIDE);
        const float4* k1p = (const float4*)(KS + (si + 64) * KSTRIDE);

        #pragma unroll 4
        for (int e4 = 0; e4 < E_/4; ++e4) {
            const float4 w4 = wv[e4];
            const float4 k0 = k0p[e4];
            const float4 k1 = k1p[e4];
            const float4 t0 = tqp[e4];
            const float4 t1 = tqp[8  + e4];
            const float4 t2 = tqp[16 + e4];
            const float4 t3 = tqp[24 + e4];
            upd(t0.x,k0.x,w4.x,a00); upd(t1.x,k0.x,w4.x,a01); upd(t2.x,k0.x,w4.x,a02); upd(t3.x,k0.x,w4.x,a03);
            upd(t0.x,k1.x,w4.x,a10); upd(t1.x,k1.x,w4.x,a11); upd(t2.x,k1.x,w4.x,a12); upd(t3.x,k1.x,w4.x,a13);
            upd(t0.y,k0.y,w4.y,a00); upd(t1.y,k0.y,w4.y,a01); upd(t2.y,k0.y,w4.y,a02); upd(t3.y,k0.y,w4.y,a03);
            upd(t0.y,k1.y,w4.y,a10); upd(t1.y,k1.y,w4.y,a11); upd(t2.y,k1.y,w4.y,a12); upd(t3.y,k1.y,w4.y,a13);
            upd(t0.z,k0.z,w4.z,a00); upd(t1.z,k0.z,w4.z,a01); upd(t2.z,k0.z,w4.z,a02); upd(t3.z,k0.z,w4.z,a03);
            upd(t0.z,k1.z,w4.z,a10); upd(t1.z,k1.z,w4.z,a11); upd(t2.z,k1.z,w4.z,a12); upd(t3.z,k1.z,w4.z,a13);
            upd(t0.w,k0.w,w4.w,a00); upd(t1.w,k0.w,w4.w,a01); upd(t2.w,k0.w,w4.w,a02); upd(t3.w,k0.w,w4.w,a03);
            upd(t0.w,k1.w,w4.w,a10); upd(t1.w,k1.w,w4.w,a11); upd(t2.w,k1.w,w4.w,a12); upd(t3.w,k1.w,w4.w,a13);
        }

        const int sg0 = c * SC + si, sg1 = sg0 + 64;
        const float kl0 = kl[b * S_ + sg0];
        const float kl1 = kl[b * S_ + sg1];
        const int lb = lg * 4;
        SCO[(lb+0)*S_ + sg0] = a00 + am[(size_t)(l0+lb+0)*S_ + sg0] + kl0;
        SCO[(lb+1)*S_ + sg0] = a01 + am[(size_t)(l0+lb+1)*S_ + sg0] + kl0;
        SCO[(lb+2)*S_ + sg0] = a02 + am[(size_t)(l0+lb+2)*S_ + sg0] + kl0;
        SCO[(lb+3)*S_ + sg0] = a03 + am[(size_t)(l0+lb+3)*S_ + sg0] + kl0;
        SCO[(lb+0)*S_ + sg1] = a10 + am[(size_t)(l0+lb+0)*S_ + sg1] + kl1;
        SCO[(lb+1)*S_ + sg1] = a11 + am[(size_t)(l0+lb+1)*S_ + sg1] + kl1;
        SCO[(lb+2)*S_ + sg1] = a12 + am[(size_t)(l0+lb+2)*S_ + sg1] + kl1;
        SCO[(lb+3)*S_ + sg1] = a13 + am[(size_t)(l0+lb+3)*S_ + sg1] + kl1;
        __syncthreads();
    }

    // ---- phase 2: softmax over S per l-row ----
    const int warp = t >> 5, lane = t & 31;
    for (int l = warp; l < TL; l += 8) {
        float* row = SCO + l * S_;
        float m = -1e30f;
        #pragma unroll
        for (int i = 0; i < S_/32; ++i) m = fmaxf(m, row[lane + 32*i]);
        #pragma unroll
        for (int o = 16; o; o >>= 1) m = fmaxf(m, __shfl_xor_sync(0xffffffffu, m, o));
        float sum = 0.f;
        float eb[S_/32];
        #pragma unroll
        for (int i = 0; i < S_/32; ++i) {
            float e = ex2_((row[lane + 32*i] - m) * 1.4426950408889634f);
            eb[i] = e; sum += e;
        }
        #pragma unroll
        for (int o = 16; o; o >>= 1) sum += __shfl_xor_sync(0xffffffffu, sum, o);
        const float inv = rcp_(sum);
        #pragma unroll
        for (int i = 0; i < S_/32; ++i) row[lane + 32*i] = eb[i] * inv;
    }
    __syncthreads();

    // ---- phase 3: out = A @ V ----
    const int lo = t >> 4;
    const int dg = t & 15;
    float acc0=0.f, acc1=0.f, acc2=0.f, acc3=0.f;
    for (int c = 0; c < NCH; ++c) {
        for (int i = t; i < SC * (D_/4); i += NT) {
            int r = i >> 4, d4 = i & 15;
            ((float4*)VS)[i] =
                ((const float4*)(val + ((size_t)(b * S_ + c * SC + r) * H_ + h) * D_))[d4];
        }
        __syncthreads();
        const float* arow = SCO + lo * S_ + c * SC;
        const float4* vs4 = (const float4*)VS;
        #pragma unroll 4
        for (int s = 0; s < SC; s += 4) {
            float b0 = arow[s], b1 = arow[s+1], b2 = arow[s+2], b3 = arow[s+3];
            float4 v0 = vs4[(s  )*16 + dg];
            float4 v1 = vs4[(s+1)*16 + dg];
            float4 v2 = vs4[(s+2)*16 + dg];
            float4 v3 = vs4[(s+3)*16 + dg];
            acc0 = fmaf(b0, v0.x, acc0); acc1 = fmaf(b0, v0.y, acc1);
            acc2 = fmaf(b0, v0.z, acc2); acc3 = fmaf(b0, v0.w, acc3);
            acc0 = fmaf(b1, v1.x, acc0); acc1 = fmaf(b1, v1.y, acc1);
            acc2 = fmaf(b1, v1.z, acc2); acc3 = fmaf(b1, v1.w, acc3);
            acc0 = fmaf(b2, v2.x, acc0); acc1 = fmaf(b2, v2.y, acc1);
            acc2 = fmaf(b2, v2.z, acc2); acc3 = fmaf(b2, v2.w, acc3);
            acc0 = fmaf(b3, v3.x, acc0); acc1 = fmaf(b3, v3.y, acc1);
            acc2 = fmaf(b3, v3.z, acc2); acc3 = fmaf(b3, v3.w, acc3);
        }
        __syncthreads();
    }
    float4 o4 = make_float4(acc0, acc1, acc2, acc3);
    *reinterpret_cast<float4*>(out + ((size_t)(b * L_ + l0 + lo) * H_ + h) * D_ + dg * 4) = o4;
}

// SMEM: TQ(512) + WS(32) + SCO(8192) + max(KS 128*36=4608, VS 8192) = 16928 floats
static const int SMEM_BYTES = (TL*E_ + E_ + TL*S_ + SC*D_) * (int)sizeof(float);

extern "C" void kernel_launch(void* const* d_in, const int* in_sizes, int n_in,
                              void* d_out, int out_size)
{
    const float* q   = (const float*)d_in[0];
    const float* k   = (const float*)d_in[1];
    const float* val = (const float*)d_in[2];
    const float* v   = (const float*)d_in[3];
    const float* am  = (const float*)d_in[4];
    const float* kl  = (const float*)d_in[5];
    float* out = (float*)d_out;

    tanh_pre<<<(B_*H_*L_*E_ + NT - 1) / NT, NT>>>(q, k);

    cudaFuncSetAttribute(addattn_kernel,
                         cudaFuncAttributeMaxDynamicSharedMemorySize, SMEM_BYTES);
    dim3 grid(L_ / TL, B_ * H_);
    addattn_kernel<<<grid, NT, SMEM_BYTES>>>(val, v, am, kl, out);
}

// round 3
// speedup vs baseline: 1.5033x; 1.0548x over previous
#include <cuda_runtime.h>

// Additive (Bahdanau) attention, fused, round 3.
// tanh(a+b) = (ta+tb)/(1+ta*tb). tanh(q), tanh(k) precomputed once.
// Inner element: n=FFMA(w,tq,wtk); den=FFMA(tq,tk,1); acc=FFMA(n,rcp(den),acc)
// -> 3 FMA-pipe ops + 1 MUFU per element (w*tk precomputed at chunk load).
// 3 CTAs/SM via __launch_bounds__(256,3); SMEM 71.8KB/CTA (215KB/SM).

#define B_  2
#define L_  512
#define S_  512
#define H_  8
#define E_  32
#define D_  64
#define TL  16
#define SC  128
#define NCH (S_/SC)
#define NT  256
#define KSTRIDE 36              // padded row stride (floats), conflict-free for LDS.128

__device__ float g_tq[B_*H_*L_*E_];   // [b,h,l,e]
__device__ float g_tk[B_*H_*S_*E_];   // [b,h,s,e]

__device__ __forceinline__ float rcp_(float x) {
    float r; asm("rcp.approx.f32 %0, %1;" : "=f"(r) : "f"(x)); return r;
}
__device__ __forceinline__ float ex2_(float x) {
    float r; asm("ex2.approx.f32 %0, %1;" : "=f"(r) : "f"(x)); return r;
}
__device__ __forceinline__ float tanh_acc(float x) {
    float e = ex2_(x * 2.8853900817779268f);   // 2*log2(e)
    return 1.0f - 2.0f * rcp_(e + 1.0f);
}

__global__ void __launch_bounds__(NT) tanh_pre(const float* __restrict__ q,
                                               const float* __restrict__ k)
{
    int idx = blockIdx.x * NT + threadIdx.x;     // dest index [b,h,l,e]
    if (idx >= B_*H_*L_*E_) return;
    int e = idx & 31;
    int l = (idx >> 5) & 511;
    int h = (idx >> 14) & 7;
    int b = idx >> 17;
    int src = ((b * L_ + l) * H_ + h) * E_ + e;  // L_ == S_
    g_tq[idx] = tanh_acc(q[src]);
    g_tk[idx] = tanh_acc(k[src]);
}

// a += w*(tq+tk)/(1+tq*tk), with wk = w*tk precomputed.
__device__ __forceinline__ void upd(float tq, float tk, float wk, float w, float& a) {
    float n   = fmaf(w, tq, wk);
    float den = fmaf(tq, tk, 1.0f);
    a = fmaf(n, rcp_(den), a);
}

__global__ void __launch_bounds__(NT, 3)
addattn_kernel(const float* __restrict__ val,
               const float* __restrict__ v,
               const float* __restrict__ am,
               const float* __restrict__ kl,
               float* __restrict__ out)
{
    extern __shared__ float sm[];
    float* TQ  = sm;                    // TL*E = 512
    float* WS  = TQ  + TL * E_;         // 32
    float* SCO = WS  + E_;              // TL*S = 8192
    float* KTK = SCO + TL * S_;         // SC*KSTRIDE = 4608 (tk)
    float* KWK = KTK + SC * KSTRIDE;    // SC*KSTRIDE = 4608 (w*tk)
    float* VS  = KTK;                   // union: SC*D = 8192 <= 9216

    const int t  = threadIdx.x;
    const int bh = blockIdx.y;
    const int b  = bh >> 3, h = bh & 7;
    const int l0 = blockIdx.x * TL;

    // ---- phase 0 ----
    if (t < E_) WS[t] = v[t];
    {
        const float* tq_src = g_tq + ((size_t)bh * L_ + l0) * E_;
        for (int i = t; i < TL * E_; i += NT) TQ[i] = tq_src[i];
    }
    __syncthreads();

    // ---- phase 1: scores ----
    const int si = t & 63;
    const int lg = t >> 6;
    const float4* wv  = (const float4*)WS;
    const float4* tqp = (const float4*)(TQ + lg * 4 * E_);

    for (int c = 0; c < NCH; ++c) {
        {
            const float4* ksrc = (const float4*)(g_tk + ((size_t)bh * S_ + c * SC) * E_);
            for (int i = t; i < SC * (E_/4); i += NT) {
                int r = i >> 3, e4 = i & 7;
                float4 kk = ksrc[i];
                float4 w4 = wv[e4];
                ((float4*)(KTK + r * KSTRIDE))[e4] = kk;
                ((float4*)(KWK + r * KSTRIDE))[e4] =
                    make_float4(kk.x*w4.x, kk.y*w4.y, kk.z*w4.z, kk.w*w4.w);
            }
        }
        __syncthreads();

        float a00=0.f,a01=0.f,a02=0.f,a03=0.f;
        float a10=0.f,a11=0.f,a12=0.f,a13=0.f;
        const float4* k0t = (const float4*)(KTK + si * KSTRIDE);
        const float4* k0w = (const float4*)(KWK + si * KSTRIDE);
        const float4* k1t = (const float4*)(KTK + (si + 64) * KSTRIDE);
        const float4* k1w = (const float4*)(KWK + (si + 64) * KSTRIDE);

        #pragma unroll 4
        for (int e4 = 0; e4 < E_/4; ++e4) {
            const float4 w4  = wv[e4];
            const float4 k0  = k0t[e4];
            const float4 kw0 = k0w[e4];
            const float4 k1  = k1t[e4];
            const float4 kw1 = k1w[e4];
            const float4 t0 = tqp[e4];
            const float4 t1 = tqp[8  + e4];
            const float4 t2 = tqp[16 + e4];
            const float4 t3 = tqp[24 + e4];
            upd(t0.x,k0.x,kw0.x,w4.x,a00); upd(t1.x,k0.x,kw0.x,w4.x,a01);
            upd(t2.x,k0.x,kw0.x,w4.x,a02); upd(t3.x,k0.x,kw0.x,w4.x,a03);
            upd(t0.x,k1.x,kw1.x,w4.x,a10); upd(t1.x,k1.x,kw1.x,w4.x,a11);
            upd(t2.x,k1.x,kw1.x,w4.x,a12); upd(t3.x,k1.x,kw1.x,w4.x,a13);
            upd(t0.y,k0.y,kw0.y,w4.y,a00); upd(t1.y,k0.y,kw0.y,w4.y,a01);
            upd(t2.y,k0.y,kw0.y,w4.y,a02); upd(t3.y,k0.y,kw0.y,w4.y,a03);
            upd(t0.y,k1.y,kw1.y,w4.y,a10); upd(t1.y,k1.y,kw1.y,w4.y,a11);
            upd(t2.y,k1.y,kw1.y,w4.y,a12); upd(t3.y,k1.y,kw1.y,w4.y,a13);
            upd(t0.z,k0.z,kw0.z,w4.z,a00); upd(t1.z,k0.z,kw0.z,w4.z,a01);
            upd(t2.z,k0.z,kw0.z,w4.z,a02); upd(t3.z,k0.z,kw0.z,w4.z,a03);
            upd(t0.z,k1.z,kw1.z,w4.z,a10); upd(t1.z,k1.z,kw1.z,w4.z,a11);
            upd(t2.z,k1.z,kw1.z,w4.z,a12); upd(t3.z,k1.z,kw1.z,w4.z,a13);
            upd(t0.w,k0.w,kw0.w,w4.w,a00); upd(t1.w,k0.w,kw0.w,w4.w,a01);
            upd(t2.w,k0.w,kw0.w,w4.w,a02); upd(t3.w,k0.w,kw0.w,w4.w,a03);
            upd(t0.w,k1.w,kw1.w,w4.w,a10); upd(t1.w,k1.w,kw1.w,w4.w,a11);
            upd(t2.w,k1.w,kw1.w,w4.w,a12); upd(t3.w,k1.w,kw1.w,w4.w,a13);
        }

        const int sg0 = c * SC + si, sg1 = sg0 + 64;
        const float kl0 = kl[b * S_ + sg0];
        const float kl1 = kl[b * S_ + sg1];
        const int lb = lg * 4;
        SCO[(lb+0)*S_ + sg0] = a00 + am[(size_t)(l0+lb+0)*S_ + sg0] + kl0;
        SCO[(lb+1)*S_ + sg0] = a01 + am[(size_t)(l0+lb+1)*S_ + sg0] + kl0;
        SCO[(lb+2)*S_ + sg0] = a02 + am[(size_t)(l0+lb+2)*S_ + sg0] + kl0;
        SCO[(lb+3)*S_ + sg0] = a03 + am[(size_t)(l0+lb+3)*S_ + sg0] + kl0;
        SCO[(lb+0)*S_ + sg1] = a10 + am[(size_t)(l0+lb+0)*S_ + sg1] + kl1;
        SCO[(lb+1)*S_ + sg1] = a11 + am[(size_t)(l0+lb+1)*S_ + sg1] + kl1;
        SCO[(lb+2)*S_ + sg1] = a12 + am[(size_t)(l0+lb+2)*S_ + sg1] + kl1;
        SCO[(lb+3)*S_ + sg1] = a13 + am[(size_t)(l0+lb+3)*S_ + sg1] + kl1;
        __syncthreads();
    }

    // ---- phase 2: softmax over S per l-row ----
    const int warp = t >> 5, lane = t & 31;
    for (int l = warp; l < TL; l += 8) {
        float* row = SCO + l * S_;
        float m = -1e30f;
        #pragma unroll
        for (int i = 0; i < S_/32; ++i) m = fmaxf(m, row[lane + 32*i]);
        #pragma unroll
        for (int o = 16; o; o >>= 1) m = fmaxf(m, __shfl_xor_sync(0xffffffffu, m, o));
        float sum = 0.f;
        float eb[S_/32];
        #pragma unroll
        for (int i = 0; i < S_/32; ++i) {
            float e = ex2_((row[lane + 32*i] - m) * 1.4426950408889634f);
            eb[i] = e; sum += e;
        }
        #pragma unroll
        for (int o = 16; o; o >>= 1) sum += __shfl_xor_sync(0xffffffffu, sum, o);
        const float inv = rcp_(sum);
        #pragma unroll
        for (int i = 0; i < S_/32; ++i) row[lane + 32*i] = eb[i] * inv;
    }
    __syncthreads();

    // ---- phase 3: out = A @ V ----
    const int lo = t >> 4;
    const int dg = t & 15;
    float acc0=0.f, acc1=0.f, acc2=0.f, acc3=0.f;
    for (int c = 0; c < NCH; ++c) {
        for (int i = t; i < SC * (D_/4); i += NT) {
            int r = i >> 4, d4 = i & 15;
            ((float4*)VS)[i] =
                ((const float4*)(val + ((size_t)(b * S_ + c * SC + r) * H_ + h) * D_))[d4];
        }
        __syncthreads();
        const float* arow = SCO + lo * S_ + c * SC;
        const float4* vs4 = (const float4*)VS;
        #pragma unroll 4
        for (int s = 0; s < SC; s += 4) {
            float b0 = arow[s], b1 = arow[s+1], b2 = arow[s+2], b3 = arow[s+3];
            float4 v0 = vs4[(s  )*16 + dg];
            float4 v1 = vs4[(s+1)*16 + dg];
            float4 v2 = vs4[(s+2)*16 + dg];
            float4 v3 = vs4[(s+3)*16 + dg];
            acc0 = fmaf(b0, v0.x, acc0); acc1 = fmaf(b0, v0.y, acc1);
            acc2 = fmaf(b0, v0.z, acc2); acc3 = fmaf(b0, v0.w, acc3);
            acc0 = fmaf(b1, v1.x, acc0); acc1 = fmaf(b1, v1.y, acc1);
            acc2 = fmaf(b1, v1.z, acc2); acc3 = fmaf(b1, v1.w, acc3);
            acc0 = fmaf(b2, v2.x, acc0); acc1 = fmaf(b2, v2.y, acc1);
            acc2 = fmaf(b2, v2.z, acc2); acc3 = fmaf(b2, v2.w, acc3);
            acc0 = fmaf(b3, v3.x, acc0); acc1 = fmaf(b3, v3.y, acc1);
            acc2 = fmaf(b3, v3.z, acc2); acc3 = fmaf(b3, v3.w, acc3);
        }
        __syncthreads();
    }
    float4 o4 = make_float4(acc0, acc1, acc2, acc3);
    *reinterpret_cast<float4*>(out + ((size_t)(b * L_ + l0 + lo) * H_ + h) * D_ + dg * 4) = o4;
}

// SMEM: 512 + 32 + 8192 + 2*4608 = 17952 floats = 71808 bytes
static const int SMEM_BYTES = (TL*E_ + E_ + TL*S_ + 2*SC*KSTRIDE) * (int)sizeof(float);

extern "C" void kernel_launch(void* const* d_in, const int* in_sizes, int n_in,
                              void* d_out, int out_size)
{
    const float* q   = (const float*)d_in[0];
    const float* k   = (const float*)d_in[1];
    const float* val = (const float*)d_in[2];
    const float* v   = (const float*)d_in[3];
    const float* am  = (const float*)d_in[4];
    const float* kl  = (const float*)d_in[5];
    float* out = (float*)d_out;

    tanh_pre<<<(B_*H_*L_*E_ + NT - 1) / NT, NT>>>(q, k);

    cudaFuncSetAttribute(addattn_kernel,
                         cudaFuncAttributeMaxDynamicSharedMemorySize, SMEM_BYTES);
    dim3 grid(L_ / TL, B_ * H_);
    addattn_kernel<<<grid, NT, SMEM_BYTES>>>(val, v, am, kl, out);
}